// round 7
// baseline (speedup 1.0000x reference)
#include <cuda_runtime.h>
#include <cuda_fp16.h>
#include <math.h>

#define D_HID   128
#define MAX_G   16384
#define MAX_N   65536
#define SCAN_T  256

// Scratch (allocation-free rule: __device__ globals)
__device__ __half g_H16[(size_t)MAX_N * D_HID];   // 16 MB fp16 copy of H
__device__ int    g_off[MAX_G + 1];

// ---------------------------------------------------------------------------
// Kernel A (merged): blocks [0, nconv) convert H f32 -> fp16 with 16B stores;
// blocks [nconv, nconv+nscan) do the exclusive scan of port_len -> g_off.
// ---------------------------------------------------------------------------
__global__ void __launch_bounds__(SCAN_T)
prolog_kernel(const float4* __restrict__ H4, int n16,
              const int* __restrict__ plen, int G, int nconv) {
    const int tid = threadIdx.x;

    if (blockIdx.x < nconv) {
        const int base = blockIdx.x * (SCAN_T * 4) + tid;
        #pragma unroll
        for (int k = 0; k < 4; k++) {
            const int i = base + k * SCAN_T;
            if (i < n16) {
                const float4 v0 = H4[2 * i];
                const float4 v1 = H4[2 * i + 1];
                __half2 a = __floats2half2_rn(v0.x, v0.y);
                __half2 b = __floats2half2_rn(v0.z, v0.w);
                __half2 cc = __floats2half2_rn(v1.x, v1.y);
                __half2 d = __floats2half2_rn(v1.z, v1.w);
                uint4 u;
                u.x = *reinterpret_cast<unsigned int*>(&a);
                u.y = *reinterpret_cast<unsigned int*>(&b);
                u.z = *reinterpret_cast<unsigned int*>(&cc);
                u.w = *reinterpret_cast<unsigned int*>(&d);
                reinterpret_cast<uint4*>(g_H16)[i] = u;
            }
        }
        return;
    }

    // ---- scan ----
    const int blk = blockIdx.x - nconv;
    int pre = 0;
    const int lim = blk * SCAN_T;
    for (int i = tid; i < lim; i += SCAN_T) pre += plen[i];

    __shared__ int red[SCAN_T];
    red[tid] = pre;
    __syncthreads();
    for (int off = SCAN_T / 2; off > 0; off >>= 1) {
        if (tid < off) red[tid] += red[tid + off];
        __syncthreads();
    }
    const int base = red[0];
    __syncthreads();

    const int idx = lim + tid;
    const int v = (idx < G) ? plen[idx] : 0;
    __shared__ int sc[SCAN_T];
    sc[tid] = v;
    __syncthreads();
    for (int off = 1; off < SCAN_T; off <<= 1) {
        int t = (tid >= off) ? sc[tid - off] : 0;
        __syncthreads();
        sc[tid] += t;
        __syncthreads();
    }
    if (idx < G)      g_off[idx] = base + sc[tid] - v;
    if (idx == G - 1) g_off[G]   = base + sc[tid];
}

// ---------------------------------------------------------------------------
// Kernel B: fused per-sample kernel — ONE WARP PER SAMPLE, no block syncs.
// 128-thread blocks (4 warps), 12 blocks/SM target for 75% occupancy.
// lane = (slot s = lane>>4 in {0,1}, chunk c = lane&15).
// ---------------------------------------------------------------------------
__global__ void __launch_bounds__(128, 12)
fused_kernel(const float* __restrict__ H,
             const float* __restrict__ w,
             const int*   __restrict__ nodes,
             const int*   __restrict__ anchor_idx,
             const int*   __restrict__ pf_gid,
             float*       __restrict__ out,
             int B, int G) {
    const int wslot = threadIdx.x >> 5;
    const int b     = blockIdx.x * 4 + wslot;
    if (b >= B) return;
    const int lane = threadIdx.x & 31;
    const int s    = lane >> 4;
    const int c    = lane & 15;

    const int g = pf_gid[b];
    const bool valid = (g >= 0) && (g < G);
    const int gc = min(max(g, 0), G - 1);
    const int anchor = anchor_idx[b];
    const int start = g_off[gc];
    const int end   = g_off[gc + 1];

    __shared__ float sw[4][64];
    __shared__ int   sn[4][64];

    float acc[8];
    #pragma unroll
    for (int k = 0; k < 8; k++) acc[k] = 0.f;
    float wa = 0.f, ws = 0.f, swa = 0.f, sws = 0.f;

    for (int base = start; base < end; base += 64) {
        const int cnt = min(64, end - base);
        // stage two lines per lane
        if (lane < cnt) {
            const float ww = w[base + lane];
            const int   nd = nodes[base + lane];
            const float wwa = fabsf(ww);
            ws += ww; wa += wwa;
            if (nd == anchor) { sws += ww; swa += wwa; }
            sw[wslot][lane] = wwa;
            sn[wslot][lane] = nd;
        }
        if (32 + lane < cnt) {
            const float ww = w[base + 32 + lane];
            const int   nd = nodes[base + 32 + lane];
            const float wwa = fabsf(ww);
            ws += ww; wa += wwa;
            if (nd == anchor) { sws += ww; swa += wwa; }
            sw[wslot][32 + lane] = wwa;
            sn[wslot][32 + lane] = nd;
        }
        __syncwarp();

        if (cnt == 64) {
            // fast path: full tile, 32 iterations per lane, deep unroll
            #pragma unroll 8
            for (int j = s; j < 64; j += 2) {
                const float ww = sw[wslot][j];
                const uint4 u = *reinterpret_cast<const uint4*>(
                    g_H16 + (size_t)sn[wslot][j] * D_HID + c * 8);
                const float2 f0 = __half22float2(*reinterpret_cast<const __half2*>(&u.x));
                const float2 f1 = __half22float2(*reinterpret_cast<const __half2*>(&u.y));
                const float2 f2 = __half22float2(*reinterpret_cast<const __half2*>(&u.z));
                const float2 f3 = __half22float2(*reinterpret_cast<const __half2*>(&u.w));
                acc[0] += ww * f0.x;  acc[1] += ww * f0.y;
                acc[2] += ww * f1.x;  acc[3] += ww * f1.y;
                acc[4] += ww * f2.x;  acc[5] += ww * f2.y;
                acc[6] += ww * f3.x;  acc[7] += ww * f3.y;
            }
        } else {
            #pragma unroll 4
            for (int j = s; j < cnt; j += 2) {
                const float ww = sw[wslot][j];
                const uint4 u = *reinterpret_cast<const uint4*>(
                    g_H16 + (size_t)sn[wslot][j] * D_HID + c * 8);
                const float2 f0 = __half22float2(*reinterpret_cast<const __half2*>(&u.x));
                const float2 f1 = __half22float2(*reinterpret_cast<const __half2*>(&u.y));
                const float2 f2 = __half22float2(*reinterpret_cast<const __half2*>(&u.z));
                const float2 f3 = __half22float2(*reinterpret_cast<const __half2*>(&u.w));
                acc[0] += ww * f0.x;  acc[1] += ww * f0.y;
                acc[2] += ww * f1.x;  acc[3] += ww * f1.y;
                acc[4] += ww * f2.x;  acc[5] += ww * f2.y;
                acc[6] += ww * f3.x;  acc[7] += ww * f3.y;
            }
        }
        __syncwarp();
    }

    // ---- combine the 2 slots ----
    #pragma unroll
    for (int k = 0; k < 8; k++)
        acc[k] += __shfl_xor_sync(0xffffffff, acc[k], 16);

    // ---- scalar sums: full-warp shuffle reduce ----
    #pragma unroll
    for (int o = 16; o > 0; o >>= 1) {
        wa  += __shfl_xor_sync(0xffffffff, wa,  o);
        ws  += __shfl_xor_sync(0xffffffff, ws,  o);
        swa += __shfl_xor_sync(0xffffffff, swa, o);
        sws += __shfl_xor_sync(0xffffffff, sws, o);
    }

    // ---- anchor row (f32), dims c*8 .. c*8+7 ----
    const float4* Ha4 = reinterpret_cast<const float4*>(H + (size_t)anchor * D_HID);
    const float4 h0 = Ha4[2 * c];
    const float4 h1 = Ha4[2 * c + 1];
    const float ha[8] = { h0.x, h0.y, h0.z, h0.w, h1.x, h1.y, h1.z, h1.w };

    const float denom = fmaxf(wa - swa, 1e-12f);
    const float inv_d = 1.f / denom;
    const float sscale = (ws - sws) * inv_d;

    float v[8], vs[8];
    float nv = 0.f, nq = 0.f;
    #pragma unroll
    for (int k = 0; k < 8; k++) {
        float vk = (acc[k] - swa * ha[k]) * inv_d;
        if (!valid) vk = 0.f;
        v[k] = vk;
        const float vq = (valid ? sscale : 0.f) * vk;
        vs[k] = vq;
        nv += vk * vk;
        nq += vq * vq;
    }
    #pragma unroll
    for (int o = 8; o > 0; o >>= 1) {
        nv += __shfl_xor_sync(0xffffffff, nv, o);
        nq += __shfl_xor_sync(0xffffffff, nq, o);
    }
    const float na = sqrtf(nv);
    const float ns = sqrtf(nq);

    // lanes 0-15 store V_abs, lanes 16-31 store V_sgn
    float o8[8];
    float* dst;
    if (s == 0) {
        const float inv = 1.f / fmaxf(na, 1e-6f);
        #pragma unroll
        for (int k = 0; k < 8; k++) o8[k] = v[k] * inv;
        dst = out + (size_t)b * D_HID + c * 8;
    } else {
        const float inv = (ns > 0.f) ? 1.f / fmaxf(ns, 1e-6f) : 1.f;
        #pragma unroll
        for (int k = 0; k < 8; k++) o8[k] = vs[k] * inv;
        dst = out + (size_t)(B + b) * D_HID + c * 8;
    }
    reinterpret_cast<float4*>(dst)[0] = make_float4(o8[0], o8[1], o8[2], o8[3]);
    reinterpret_cast<float4*>(dst)[1] = make_float4(o8[4], o8[5], o8[6], o8[7]);
}

// ---------------------------------------------------------------------------
extern "C" void kernel_launch(void* const* d_in, const int* in_sizes, int n_in,
                              void* d_out, int out_size) {
    const float* H      = (const float*)d_in[0];   // [N, 128]
    const float* w      = (const float*)d_in[1];   // [L]
    const int*   anchor = (const int*)  d_in[2];   // [B]
    const int*   pfgid  = (const int*)  d_in[3];   // [B]
    const int*   nodes  = (const int*)  d_in[4];   // [L]
    const int*   plen   = (const int*)  d_in[5];   // [G]
    float* out = (float*)d_out;                    // [2, B, 128]

    const int B = in_sizes[2];
    const int G = in_sizes[5];
    const int n16 = in_sizes[0] / 8;               // uint4 groups of fp16 out
    const int nconv = (n16 + SCAN_T * 4 - 1) / (SCAN_T * 4);
    const int nscan = (G + SCAN_T - 1) / SCAN_T;

    prolog_kernel<<<nconv + nscan, SCAN_T>>>((const float4*)H, n16, plen, G, nconv);
    fused_kernel<<<(B + 3) / 4, 128>>>(H, w, nodes, anchor, pfgid, out, B, G);
}

// round 8
// speedup vs baseline: 1.1136x; 1.1136x over previous
#include <cuda_runtime.h>
#include <cuda_fp16.h>
#include <math.h>

#define D_HID   128
#define MAX_G   16384
#define MAX_N   65536
#define SCAN_T  256

// Scratch (allocation-free rule: __device__ globals)
__device__ __half g_H16[(size_t)MAX_N * D_HID];   // 16 MB fp16 copy of H
__device__ int    g_off[MAX_G + 1];

// ---------------------------------------------------------------------------
// packed f32x2 helpers (SASS FFMA2 — PTX-only pattern)
// ---------------------------------------------------------------------------
__device__ __forceinline__ unsigned long long pack2(float lo, float hi) {
    unsigned long long r;
    asm("mov.b64 %0, {%1, %2};" : "=l"(r) : "f"(lo), "f"(hi));
    return r;
}
__device__ __forceinline__ void ffma2(unsigned long long& acc,
                                      unsigned long long a,
                                      unsigned long long b) {
    asm("fma.rn.f32x2 %0, %1, %2, %0;" : "+l"(acc) : "l"(a), "l"(b));
}
__device__ __forceinline__ float2 unpack2(unsigned long long v) {
    float2 f;
    asm("mov.b64 {%0, %1}, %2;" : "=f"(f.x), "=f"(f.y) : "l"(v));
    return f;
}

// ---------------------------------------------------------------------------
// Kernel A (merged): blocks [0, nconv) convert H f32 -> fp16 with 16B stores;
// blocks [nconv, nconv+nscan) do the exclusive scan of port_len -> g_off.
// ---------------------------------------------------------------------------
__global__ void __launch_bounds__(SCAN_T)
prolog_kernel(const float4* __restrict__ H4, int n16,
              const int* __restrict__ plen, int G, int nconv) {
    const int tid = threadIdx.x;

    if (blockIdx.x < nconv) {
        const int base = blockIdx.x * (SCAN_T * 4) + tid;
        #pragma unroll
        for (int k = 0; k < 4; k++) {
            const int i = base + k * SCAN_T;
            if (i < n16) {
                const float4 v0 = H4[2 * i];
                const float4 v1 = H4[2 * i + 1];
                __half2 a = __floats2half2_rn(v0.x, v0.y);
                __half2 b = __floats2half2_rn(v0.z, v0.w);
                __half2 cc = __floats2half2_rn(v1.x, v1.y);
                __half2 d = __floats2half2_rn(v1.z, v1.w);
                uint4 u;
                u.x = *reinterpret_cast<unsigned int*>(&a);
                u.y = *reinterpret_cast<unsigned int*>(&b);
                u.z = *reinterpret_cast<unsigned int*>(&cc);
                u.w = *reinterpret_cast<unsigned int*>(&d);
                reinterpret_cast<uint4*>(g_H16)[i] = u;
            }
        }
        return;
    }

    // ---- scan ----
    const int blk = blockIdx.x - nconv;
    int pre = 0;
    const int lim = blk * SCAN_T;
    for (int i = tid; i < lim; i += SCAN_T) pre += plen[i];

    __shared__ int red[SCAN_T];
    red[tid] = pre;
    __syncthreads();
    for (int off = SCAN_T / 2; off > 0; off >>= 1) {
        if (tid < off) red[tid] += red[tid + off];
        __syncthreads();
    }
    const int base = red[0];
    __syncthreads();

    const int idx = lim + tid;
    const int v = (idx < G) ? plen[idx] : 0;
    __shared__ int sc[SCAN_T];
    sc[tid] = v;
    __syncthreads();
    for (int off = 1; off < SCAN_T; off <<= 1) {
        int t = (tid >= off) ? sc[tid - off] : 0;
        __syncthreads();
        sc[tid] += t;
        __syncthreads();
    }
    if (idx < G)      g_off[idx] = base + sc[tid] - v;
    if (idx == G - 1) g_off[G]   = base + sc[tid];
}

// ---------------------------------------------------------------------------
// Kernel B: fused per-sample kernel — ONE WARP PER SAMPLE (R6 structure).
// 256-thread blocks, no reg cap. Packed FFMA2 accumulation.
// ---------------------------------------------------------------------------
__global__ void __launch_bounds__(256)
fused_kernel(const float* __restrict__ H,
             const float* __restrict__ w,
             const int*   __restrict__ nodes,
             const int*   __restrict__ anchor_idx,
             const int*   __restrict__ pf_gid,
             float*       __restrict__ out,
             int B, int G) {
    const int wslot = threadIdx.x >> 5;
    const int b     = blockIdx.x * 8 + wslot;
    if (b >= B) return;
    const int lane = threadIdx.x & 31;
    const int s    = lane >> 4;
    const int c    = lane & 15;

    const int g = pf_gid[b];
    const bool valid = (g >= 0) && (g < G);
    const int gc = min(max(g, 0), G - 1);
    const int anchor = anchor_idx[b];
    const int start = g_off[gc];
    const int end   = g_off[gc + 1];

    __shared__ float sw[8][64];
    __shared__ int   sn[8][64];

    unsigned long long a0 = pack2(0.f, 0.f), a1 = a0, a2 = a0, a3 = a0;
    float wa = 0.f, ws = 0.f, swa = 0.f, sws = 0.f;

    for (int base = start; base < end; base += 64) {
        const int cnt = min(64, end - base);
        // stage two consecutive lines per lane (vectorized when safe)
        if (2 * lane + 1 < cnt) {
            const float2 w2 = *reinterpret_cast<const float2*>(w + base + 2 * lane);
            const int2   n2 = *reinterpret_cast<const int2*>(nodes + base + 2 * lane);
            const float wa0 = fabsf(w2.x), wa1 = fabsf(w2.y);
            ws += w2.x + w2.y;
            wa += wa0 + wa1;
            if (n2.x == anchor) { sws += w2.x; swa += wa0; }
            if (n2.y == anchor) { sws += w2.y; swa += wa1; }
            *reinterpret_cast<float2*>(&sw[wslot][2 * lane]) = make_float2(wa0, wa1);
            *reinterpret_cast<int2*>(&sn[wslot][2 * lane]) = n2;
        } else if (2 * lane < cnt) {
            const float ww = w[base + 2 * lane];
            const int   nd = nodes[base + 2 * lane];
            const float wwa = fabsf(ww);
            ws += ww; wa += wwa;
            if (nd == anchor) { sws += ww; swa += wwa; }
            sw[wslot][2 * lane] = wwa;
            sn[wslot][2 * lane] = nd;
        }
        __syncwarp();

        if (cnt == 64) {
            #pragma unroll 8
            for (int j = s; j < 64; j += 2) {
                const unsigned long long wp = pack2(sw[wslot][j], sw[wslot][j]);
                const uint4 u = *reinterpret_cast<const uint4*>(
                    g_H16 + (size_t)sn[wslot][j] * D_HID + c * 8);
                const float2 f0 = __half22float2(*reinterpret_cast<const __half2*>(&u.x));
                const float2 f1 = __half22float2(*reinterpret_cast<const __half2*>(&u.y));
                const float2 f2 = __half22float2(*reinterpret_cast<const __half2*>(&u.z));
                const float2 f3 = __half22float2(*reinterpret_cast<const __half2*>(&u.w));
                ffma2(a0, pack2(f0.x, f0.y), wp);
                ffma2(a1, pack2(f1.x, f1.y), wp);
                ffma2(a2, pack2(f2.x, f2.y), wp);
                ffma2(a3, pack2(f3.x, f3.y), wp);
            }
        } else {
            #pragma unroll 4
            for (int j = s; j < cnt; j += 2) {
                const unsigned long long wp = pack2(sw[wslot][j], sw[wslot][j]);
                const uint4 u = *reinterpret_cast<const uint4*>(
                    g_H16 + (size_t)sn[wslot][j] * D_HID + c * 8);
                const float2 f0 = __half22float2(*reinterpret_cast<const __half2*>(&u.x));
                const float2 f1 = __half22float2(*reinterpret_cast<const __half2*>(&u.y));
                const float2 f2 = __half22float2(*reinterpret_cast<const __half2*>(&u.z));
                const float2 f3 = __half22float2(*reinterpret_cast<const __half2*>(&u.w));
                ffma2(a0, pack2(f0.x, f0.y), wp);
                ffma2(a1, pack2(f1.x, f1.y), wp);
                ffma2(a2, pack2(f2.x, f2.y), wp);
                ffma2(a3, pack2(f3.x, f3.y), wp);
            }
        }
        __syncwarp();
    }

    // unpack accumulators
    float acc[8];
    {
        const float2 r0 = unpack2(a0), r1 = unpack2(a1);
        const float2 r2 = unpack2(a2), r3 = unpack2(a3);
        acc[0] = r0.x; acc[1] = r0.y; acc[2] = r1.x; acc[3] = r1.y;
        acc[4] = r2.x; acc[5] = r2.y; acc[6] = r3.x; acc[7] = r3.y;
    }

    // ---- combine the 2 slots ----
    #pragma unroll
    for (int k = 0; k < 8; k++)
        acc[k] += __shfl_xor_sync(0xffffffff, acc[k], 16);

    // ---- scalar sums: full-warp shuffle reduce ----
    #pragma unroll
    for (int o = 16; o > 0; o >>= 1) {
        wa  += __shfl_xor_sync(0xffffffff, wa,  o);
        ws  += __shfl_xor_sync(0xffffffff, ws,  o);
        swa += __shfl_xor_sync(0xffffffff, swa, o);
        sws += __shfl_xor_sync(0xffffffff, sws, o);
    }

    // ---- anchor row (f32), dims c*8 .. c*8+7 ----
    const float4* Ha4 = reinterpret_cast<const float4*>(H + (size_t)anchor * D_HID);
    const float4 h0 = Ha4[2 * c];
    const float4 h1 = Ha4[2 * c + 1];
    const float ha[8] = { h0.x, h0.y, h0.z, h0.w, h1.x, h1.y, h1.z, h1.w };

    const float denom = fmaxf(wa - swa, 1e-12f);
    const float inv_d = 1.f / denom;
    const float sscale = (ws - sws) * inv_d;

    float v[8], vs[8];
    float nv = 0.f, nq = 0.f;
    #pragma unroll
    for (int k = 0; k < 8; k++) {
        float vk = (acc[k] - swa * ha[k]) * inv_d;
        if (!valid) vk = 0.f;
        v[k] = vk;
        const float vq = (valid ? sscale : 0.f) * vk;
        vs[k] = vq;
        nv += vk * vk;
        nq += vq * vq;
    }
    #pragma unroll
    for (int o = 8; o > 0; o >>= 1) {
        nv += __shfl_xor_sync(0xffffffff, nv, o);
        nq += __shfl_xor_sync(0xffffffff, nq, o);
    }
    const float na = sqrtf(nv);
    const float ns = sqrtf(nq);

    // lanes 0-15 store V_abs, lanes 16-31 store V_sgn
    float o8[8];
    float* dst;
    if (s == 0) {
        const float inv = 1.f / fmaxf(na, 1e-6f);
        #pragma unroll
        for (int k = 0; k < 8; k++) o8[k] = v[k] * inv;
        dst = out + (size_t)b * D_HID + c * 8;
    } else {
        const float inv = (ns > 0.f) ? 1.f / fmaxf(ns, 1e-6f) : 1.f;
        #pragma unroll
        for (int k = 0; k < 8; k++) o8[k] = vs[k] * inv;
        dst = out + (size_t)(B + b) * D_HID + c * 8;
    }
    reinterpret_cast<float4*>(dst)[0] = make_float4(o8[0], o8[1], o8[2], o8[3]);
    reinterpret_cast<float4*>(dst)[1] = make_float4(o8[4], o8[5], o8[6], o8[7]);
}

// ---------------------------------------------------------------------------
extern "C" void kernel_launch(void* const* d_in, const int* in_sizes, int n_in,
                              void* d_out, int out_size) {
    const float* H      = (const float*)d_in[0];   // [N, 128]
    const float* w      = (const float*)d_in[1];   // [L]
    const int*   anchor = (const int*)  d_in[2];   // [B]
    const int*   pfgid  = (const int*)  d_in[3];   // [B]
    const int*   nodes  = (const int*)  d_in[4];   // [L]
    const int*   plen   = (const int*)  d_in[5];   // [G]
    float* out = (float*)d_out;                    // [2, B, 128]

    const int B = in_sizes[2];
    const int G = in_sizes[5];
    const int n16 = in_sizes[0] / 8;               // uint4 groups of fp16 out
    const int nconv = (n16 + SCAN_T * 4 - 1) / (SCAN_T * 4);
    const int nscan = (G + SCAN_T - 1) / SCAN_T;

    prolog_kernel<<<nconv + nscan, SCAN_T>>>((const float4*)H, n16, plen, G, nconv);
    fused_kernel<<<(B + 7) / 8, 256>>>(H, w, nodes, anchor, pfgid, out, B, G);
}

// round 9
// speedup vs baseline: 1.1384x; 1.0223x over previous
#include <cuda_runtime.h>
#include <cuda_fp16.h>
#include <math.h>

#define D_HID   128
#define MAX_G   16384
#define MAX_N   65536
#define SCAN_T  256

// Scratch (allocation-free rule: __device__ globals)
__device__ __half g_H16[(size_t)MAX_N * D_HID];   // 16 MB fp16 copy of H
__device__ int    g_off[MAX_G + 1];

// ---------------------------------------------------------------------------
// packed f32x2 helpers (SASS FFMA2 — PTX-only pattern)
// ---------------------------------------------------------------------------
__device__ __forceinline__ unsigned long long pack2(float lo, float hi) {
    unsigned long long r;
    asm("mov.b64 %0, {%1, %2};" : "=l"(r) : "f"(lo), "f"(hi));
    return r;
}
__device__ __forceinline__ void ffma2(unsigned long long& acc,
                                      unsigned long long a,
                                      unsigned long long b) {
    asm("fma.rn.f32x2 %0, %1, %2, %0;" : "+l"(acc) : "l"(a), "l"(b));
}
__device__ __forceinline__ float2 unpack2(unsigned long long v) {
    float2 f;
    asm("mov.b64 {%0, %1}, %2;" : "=f"(f.x), "=f"(f.y) : "l"(v));
    return f;
}

// ---------------------------------------------------------------------------
// Kernel A (merged): blocks [0, nconv) convert H f32 -> fp16 with 16B stores;
// blocks [nconv, nconv+nscan) do the exclusive scan of port_len -> g_off.
// ---------------------------------------------------------------------------
__global__ void __launch_bounds__(SCAN_T)
prolog_kernel(const float4* __restrict__ H4, int n16,
              const int* __restrict__ plen, int G, int nconv) {
    const int tid = threadIdx.x;

    if (blockIdx.x < nconv) {
        const int base = blockIdx.x * (SCAN_T * 4) + tid;
        #pragma unroll
        for (int k = 0; k < 4; k++) {
            const int i = base + k * SCAN_T;
            if (i < n16) {
                const float4 v0 = H4[2 * i];
                const float4 v1 = H4[2 * i + 1];
                __half2 a = __floats2half2_rn(v0.x, v0.y);
                __half2 b = __floats2half2_rn(v0.z, v0.w);
                __half2 cc = __floats2half2_rn(v1.x, v1.y);
                __half2 d = __floats2half2_rn(v1.z, v1.w);
                uint4 u;
                u.x = *reinterpret_cast<unsigned int*>(&a);
                u.y = *reinterpret_cast<unsigned int*>(&b);
                u.z = *reinterpret_cast<unsigned int*>(&cc);
                u.w = *reinterpret_cast<unsigned int*>(&d);
                reinterpret_cast<uint4*>(g_H16)[i] = u;
            }
        }
        return;
    }

    // ---- scan ----
    const int blk = blockIdx.x - nconv;
    int pre = 0;
    const int lim = blk * SCAN_T;
    for (int i = tid; i < lim; i += SCAN_T) pre += plen[i];

    __shared__ int red[SCAN_T];
    red[tid] = pre;
    __syncthreads();
    for (int off = SCAN_T / 2; off > 0; off >>= 1) {
        if (tid < off) red[tid] += red[tid + off];
        __syncthreads();
    }
    const int base = red[0];
    __syncthreads();

    const int idx = lim + tid;
    const int v = (idx < G) ? plen[idx] : 0;
    __shared__ int sc[SCAN_T];
    sc[tid] = v;
    __syncthreads();
    for (int off = 1; off < SCAN_T; off <<= 1) {
        int t = (tid >= off) ? sc[tid - off] : 0;
        __syncthreads();
        sc[tid] += t;
        __syncthreads();
    }
    if (idx < G)      g_off[idx] = base + sc[tid] - v;
    if (idx == G - 1) g_off[G]   = base + sc[tid];
}

// ---------------------------------------------------------------------------
// Kernel B: fused per-sample kernel — ONE WARP PER SAMPLE.
// 256-thread blocks, FFMA2 accumulation, int2-packed staging (one LDS.64 per
// line), cp.async anchor-row prefetch hidden behind the gather loop.
// ---------------------------------------------------------------------------
__global__ void __launch_bounds__(256)
fused_kernel(const float* __restrict__ H,
             const float* __restrict__ w,
             const int*   __restrict__ nodes,
             const int*   __restrict__ anchor_idx,
             const int*   __restrict__ pf_gid,
             float*       __restrict__ out,
             int B, int G) {
    const int wslot = threadIdx.x >> 5;
    const int b     = blockIdx.x * 8 + wslot;
    if (b >= B) return;
    const int lane = threadIdx.x & 31;
    const int s    = lane >> 4;
    const int c    = lane & 15;

    const int g = pf_gid[b];
    const bool valid = (g >= 0) && (g < G);
    const int gc = min(max(g, 0), G - 1);
    const int anchor = anchor_idx[b];
    const int start = g_off[gc];
    const int end   = g_off[gc + 1];

    __shared__ int2  sm[8][64];     // {node, |w| bits}
    __shared__ float s_ha[8][128];  // prefetched f32 anchor rows

    // ---- cp.async anchor-row prefetch (zero register cost, waited in epilogue)
    {
        const float* src = H + (size_t)anchor * D_HID + lane * 4;
        const unsigned dst =
            (unsigned)__cvta_generic_to_shared(&s_ha[wslot][lane * 4]);
        asm volatile("cp.async.cg.shared.global [%0], [%1], 16;\n"
                     :: "r"(dst), "l"(src));
        asm volatile("cp.async.commit_group;\n");
    }

    unsigned long long a0 = pack2(0.f, 0.f), a1 = a0, a2 = a0, a3 = a0;
    float wa = 0.f, ws = 0.f, swa = 0.f, sws = 0.f;

    for (int base = start; base < end; base += 64) {
        const int cnt = min(64, end - base);
        // stage two consecutive lines per lane, packed {node, |w|}
        if (2 * lane + 1 < cnt) {
            const float2 w2 = *reinterpret_cast<const float2*>(w + base + 2 * lane);
            const int2   n2 = *reinterpret_cast<const int2*>(nodes + base + 2 * lane);
            const float wa0 = fabsf(w2.x), wa1 = fabsf(w2.y);
            ws += w2.x + w2.y;
            wa += wa0 + wa1;
            if (n2.x == anchor) { sws += w2.x; swa += wa0; }
            if (n2.y == anchor) { sws += w2.y; swa += wa1; }
            *reinterpret_cast<int4*>(&sm[wslot][2 * lane]) =
                make_int4(n2.x, __float_as_int(wa0), n2.y, __float_as_int(wa1));
        } else if (2 * lane < cnt) {
            const float ww = w[base + 2 * lane];
            const int   nd = nodes[base + 2 * lane];
            const float wwa = fabsf(ww);
            ws += ww; wa += wwa;
            if (nd == anchor) { sws += ww; swa += wwa; }
            sm[wslot][2 * lane] = make_int2(nd, __float_as_int(wwa));
        }
        __syncwarp();

        if (cnt == 64) {
            #pragma unroll 8
            for (int j = s; j < 64; j += 2) {
                const int2 p = sm[wslot][j];                 // one LDS.64 broadcast
                const float ww = __int_as_float(p.y);
                const unsigned long long wp = pack2(ww, ww);
                const uint4 u = *reinterpret_cast<const uint4*>(
                    g_H16 + (size_t)p.x * D_HID + c * 8);
                const float2 f0 = __half22float2(*reinterpret_cast<const __half2*>(&u.x));
                const float2 f1 = __half22float2(*reinterpret_cast<const __half2*>(&u.y));
                const float2 f2 = __half22float2(*reinterpret_cast<const __half2*>(&u.z));
                const float2 f3 = __half22float2(*reinterpret_cast<const __half2*>(&u.w));
                ffma2(a0, pack2(f0.x, f0.y), wp);
                ffma2(a1, pack2(f1.x, f1.y), wp);
                ffma2(a2, pack2(f2.x, f2.y), wp);
                ffma2(a3, pack2(f3.x, f3.y), wp);
            }
        } else {
            #pragma unroll 4
            for (int j = s; j < cnt; j += 2) {
                const int2 p = sm[wslot][j];
                const float ww = __int_as_float(p.y);
                const unsigned long long wp = pack2(ww, ww);
                const uint4 u = *reinterpret_cast<const uint4*>(
                    g_H16 + (size_t)p.x * D_HID + c * 8);
                const float2 f0 = __half22float2(*reinterpret_cast<const __half2*>(&u.x));
                const float2 f1 = __half22float2(*reinterpret_cast<const __half2*>(&u.y));
                const float2 f2 = __half22float2(*reinterpret_cast<const __half2*>(&u.z));
                const float2 f3 = __half22float2(*reinterpret_cast<const __half2*>(&u.w));
                ffma2(a0, pack2(f0.x, f0.y), wp);
                ffma2(a1, pack2(f1.x, f1.y), wp);
                ffma2(a2, pack2(f2.x, f2.y), wp);
                ffma2(a3, pack2(f3.x, f3.y), wp);
            }
        }
        __syncwarp();
    }

    // unpack accumulators
    float acc[8];
    {
        const float2 r0 = unpack2(a0), r1 = unpack2(a1);
        const float2 r2 = unpack2(a2), r3 = unpack2(a3);
        acc[0] = r0.x; acc[1] = r0.y; acc[2] = r1.x; acc[3] = r1.y;
        acc[4] = r2.x; acc[5] = r2.y; acc[6] = r3.x; acc[7] = r3.y;
    }

    // ---- combine the 2 slots ----
    #pragma unroll
    for (int k = 0; k < 8; k++)
        acc[k] += __shfl_xor_sync(0xffffffff, acc[k], 16);

    // ---- scalar sums: full-warp shuffle reduce ----
    #pragma unroll
    for (int o = 16; o > 0; o >>= 1) {
        wa  += __shfl_xor_sync(0xffffffff, wa,  o);
        ws  += __shfl_xor_sync(0xffffffff, ws,  o);
        swa += __shfl_xor_sync(0xffffffff, swa, o);
        sws += __shfl_xor_sync(0xffffffff, sws, o);
    }

    // ---- anchor row: arrived via cp.async during the gather loop ----
    asm volatile("cp.async.wait_group 0;\n");
    __syncwarp();
    const float4 h0 = *reinterpret_cast<const float4*>(&s_ha[wslot][c * 8]);
    const float4 h1 = *reinterpret_cast<const float4*>(&s_ha[wslot][c * 8 + 4]);
    const float ha[8] = { h0.x, h0.y, h0.z, h0.w, h1.x, h1.y, h1.z, h1.w };

    const float denom = fmaxf(wa - swa, 1e-12f);
    const float inv_d = 1.f / denom;
    const float sscale = (ws - sws) * inv_d;

    float v[8], vs[8];
    float nv = 0.f, nq = 0.f;
    #pragma unroll
    for (int k = 0; k < 8; k++) {
        float vk = (acc[k] - swa * ha[k]) * inv_d;
        if (!valid) vk = 0.f;
        v[k] = vk;
        const float vq = (valid ? sscale : 0.f) * vk;
        vs[k] = vq;
        nv += vk * vk;
        nq += vq * vq;
    }
    #pragma unroll
    for (int o = 8; o > 0; o >>= 1) {
        nv += __shfl_xor_sync(0xffffffff, nv, o);
        nq += __shfl_xor_sync(0xffffffff, nq, o);
    }
    const float na = sqrtf(nv);
    const float ns = sqrtf(nq);

    // lanes 0-15 store V_abs, lanes 16-31 store V_sgn
    float o8[8];
    float* dst;
    if (s == 0) {
        const float inv = 1.f / fmaxf(na, 1e-6f);
        #pragma unroll
        for (int k = 0; k < 8; k++) o8[k] = v[k] * inv;
        dst = out + (size_t)b * D_HID + c * 8;
    } else {
        const float inv = (ns > 0.f) ? 1.f / fmaxf(ns, 1e-6f) : 1.f;
        #pragma unroll
        for (int k = 0; k < 8; k++) o8[k] = vs[k] * inv;
        dst = out + (size_t)(B + b) * D_HID + c * 8;
    }
    reinterpret_cast<float4*>(dst)[0] = make_float4(o8[0], o8[1], o8[2], o8[3]);
    reinterpret_cast<float4*>(dst)[1] = make_float4(o8[4], o8[5], o8[6], o8[7]);
}

// ---------------------------------------------------------------------------
extern "C" void kernel_launch(void* const* d_in, const int* in_sizes, int n_in,
                              void* d_out, int out_size) {
    const float* H      = (const float*)d_in[0];   // [N, 128]
    const float* w      = (const float*)d_in[1];   // [L]
    const int*   anchor = (const int*)  d_in[2];   // [B]
    const int*   pfgid  = (const int*)  d_in[3];   // [B]
    const int*   nodes  = (const int*)  d_in[4];   // [L]
    const int*   plen   = (const int*)  d_in[5];   // [G]
    float* out = (float*)d_out;                    // [2, B, 128]

    const int B = in_sizes[2];
    const int G = in_sizes[5];
    const int n16 = in_sizes[0] / 8;               // uint4 groups of fp16 out
    const int nconv = (n16 + SCAN_T * 4 - 1) / (SCAN_T * 4);
    const int nscan = (G + SCAN_T - 1) / SCAN_T;

    prolog_kernel<<<nconv + nscan, SCAN_T>>>((const float4*)H, n16, plen, G, nconv);
    fused_kernel<<<(B + 7) / 8, 256>>>(H, w, nodes, anchor, pfgid, out, B, G);
}